// round 4
// baseline (speedup 1.0000x reference)
#include <cuda_runtime.h>
#include <cstdint>
#include <cstddef>

// Structure:
//   xg = X @ W_ih^T + b_ih + b_hh  precomputed per layer as a parallel GEMM
//   (layer 1 fuses the embedding gather). Recurrence kernels then only do the
//   K=64 h @ W_hh^T dot per step, with the CTA split into two independent
//   128-thread groups (one batch column each) synchronized by NAMED barriers.
//
// 6 sequential launches: gemm1, rec1, gemm2, rec2, gemm3, rec3(+softmax).

#define T_SEQ   512
#define BATCH   256
#define HID     64
#define GATES   256   // 4*HID
#define EMBD    128
#define VOCAB   50257
#define GROWS   (T_SEQ * BATCH)    // 131072 rows of xg
#define RPC     128                // rows per GEMM CTA
#define CHUNK   8                  // rows per smem chunk
#define GEMM_GRID (GROWS / RPC)    // 1024

__device__ float g_xg[(size_t)T_SEQ * BATCH * GATES];  // gate inputs (reused per layer)
__device__ float g_ha[(size_t)T_SEQ * BATCH * HID];    // layer-1 h
__device__ float g_hb[(size_t)T_SEQ * BATCH * HID];    // layer-2 h

typedef unsigned long long ull;

__device__ __forceinline__ ull pack2(float x, float y) {
    ull r; asm("mov.b64 %0, {%1,%2};" : "=l"(r) : "f"(x), "f"(y)); return r;
}
__device__ __forceinline__ void fma2(ull& acc, ull a, ull b) {
    asm("fma.rn.f32x2 %0, %1, %2, %0;" : "+l"(acc) : "l"(a), "l"(b));
}
__device__ __forceinline__ float red2(ull a) {
    float lo, hi; asm("mov.b64 {%0,%1}, %2;" : "=f"(lo), "=f"(hi) : "l"(a));
    return lo + hi;
}
__device__ __forceinline__ float fsigm(float x) {   // 1 ex2 + 1 rcp
    return __fdividef(1.0f, 1.0f + __expf(-x));
}
__device__ __forceinline__ float ftanh(float x) {   // tanh(x) = 2*sigm(2x) - 1
    return 2.0f * fsigm(2.0f * x) - 1.0f;
}

// ---------------------------------------------------------------------------
// xg GEMM: xg[r][g] = sum_k X[r][k] * W_ih[g][k] + b_ih[g] + b_hh[g]
// GATHER=1: X[r] = emb[ x[r] ]  (r = t*BATCH+b, x laid out [T][B])
// GATHER=0: X[r] = src + r*KIN  (h of previous layer, [T][B][HID] contiguous)
// ---------------------------------------------------------------------------
template <int KIN, int GATHER>
__global__ void __launch_bounds__(256, 1)
xg_gemm_kernel(const int* __restrict__ xidx,
               const float* __restrict__ src,
               const float* __restrict__ W_ih,
               const float* __restrict__ b_ih,
               const float* __restrict__ b_hh,
               float* __restrict__ xg)
{
    __shared__ __align__(16) float xs[CHUNK][KIN];
    const int tid = threadIdx.x;
    const int g = tid;                       // gate row
    const int rbase0 = blockIdx.x * RPC;

    // gate-row weights in registers as f32x2 pairs
    ull w2[KIN / 2];
    {
        const float4* wi = reinterpret_cast<const float4*>(W_ih + (size_t)g * KIN);
        #pragma unroll
        for (int q = 0; q < KIN / 4; q++) {
            float4 v = wi[q];
            w2[2 * q]     = pack2(v.x, v.y);
            w2[2 * q + 1] = pack2(v.z, v.w);
        }
    }
    const float bs = b_ih[g] + b_hh[g];

    // prefetch mapping: PF floats per thread covering CHUNK*KIN elements
    constexpr int PF = CHUNK * KIN / 256;    // 4 (KIN=128) or 2 (KIN=64)
    const int prow = (tid * PF) / KIN;       // 0..CHUNK-1
    const int pk   = (tid * PF) % KIN;       // PF-aligned

    float pf[PF];
    auto prefetch = [&](int cb) {
        int r = rbase0 + cb + prow;
        const float* sp;
        if (GATHER) {
            int tok = xidx[r];
            tok = tok < 0 ? 0 : (tok >= VOCAB ? VOCAB - 1 : tok);
            sp = src + (size_t)tok * EMBD + pk;
        } else {
            sp = src + (size_t)r * KIN + pk;
        }
        if (PF == 4) {
            float4 v = *reinterpret_cast<const float4*>(sp);
            pf[0] = v.x; pf[1] = v.y; pf[2] = v.z; pf[3] = v.w;
        } else {
            float2 v = *reinterpret_cast<const float2*>(sp);
            pf[0] = v.x; pf[1] = v.y;
        }
    };

    prefetch(0);

    for (int cb = 0; cb < RPC; cb += CHUNK) {
        __syncthreads();                       // previous compute done
        #pragma unroll
        for (int i = 0; i < PF; i++) xs[prow][pk + i] = pf[i];
        __syncthreads();
        if (cb + CHUNK < RPC) prefetch(cb + CHUNK);   // hidden under compute

        ull acc[CHUNK];
        #pragma unroll
        for (int row = 0; row < CHUNK; row++) acc[row] = 0ull;
        #pragma unroll
        for (int q = 0; q < KIN / 4; q++) {
            #pragma unroll
            for (int row = 0; row < CHUNK; row++) {
                ulonglong2 a = reinterpret_cast<const ulonglong2*>(&xs[row][0])[q];
                fma2(acc[row], w2[2 * q],     a.x);
                fma2(acc[row], w2[2 * q + 1], a.y);
            }
        }
        #pragma unroll
        for (int row = 0; row < CHUNK; row++) {
            xg[(size_t)(rbase0 + cb + row) * GATES + g] = red2(acc[row]) + bs;
        }
    }
}

// ---------------------------------------------------------------------------
// Recurrence: per step  g = xg_t + h@W_hh^T ; LSTM cell; optional softmax.
// Two independent 128-thread groups per CTA (one batch column each),
// named barriers 1/2. Thread l owns gate rows l and l+128.
// Update threads: grp0 -> l in [0,64) (SMSP 0,1); grp1 -> l in [64,128)
// (SMSP 2,3) so MUFU work balances across subpartitions.
// ---------------------------------------------------------------------------
template <int LAST>
__global__ void __launch_bounds__(256, 1)
rec_kernel(const float* __restrict__ xg,
           const float* __restrict__ W_hh,
           float* __restrict__ hout,     // LAST=0: h output buffer
           float* __restrict__ out)      // LAST=1: softmax output
{
    __shared__ __align__(16) float xh[2][HID];
    __shared__ float gsm[2][GATES];

    const int tid = threadIdx.x;
    const int grp = tid >> 7;           // 0 / 1
    const int l   = tid & 127;
    const int b   = blockIdx.x * 2 + grp;
    const int r0  = l, r1 = l + 128;

    ull w0[HID / 2], w1[HID / 2];
    {
        const float4* wa = reinterpret_cast<const float4*>(W_hh + (size_t)r0 * HID);
        const float4* wb = reinterpret_cast<const float4*>(W_hh + (size_t)r1 * HID);
        #pragma unroll
        for (int q = 0; q < HID / 4; q++) {
            float4 va = wa[q];
            w0[2 * q]     = pack2(va.x, va.y);
            w0[2 * q + 1] = pack2(va.z, va.w);
            float4 vb = wb[q];
            w1[2 * q]     = pack2(vb.x, vb.y);
            w1[2 * q + 1] = pack2(vb.z, vb.w);
        }
    }

    const bool upd = (grp == 0) ? (l < HID) : (l >= 128 - HID);
    const int  j   = (grp == 0) ? l : (l - (128 - HID));

    if (l < HID) xh[grp][l] = 0.0f;
    float c = 0.0f;
    __syncthreads();

    // prefetch xg for t=0
    float a0 = xg[(size_t)b * GATES + r0];
    float a1 = xg[(size_t)b * GATES + r1];

    for (int t = 0; t < T_SEQ; t++) {
        float n0 = 0.0f, n1 = 0.0f;
        if (t + 1 < T_SEQ) {
            size_t base = ((size_t)(t + 1) * BATCH + b) * GATES;
            n0 = xg[base + r0];
            n1 = xg[base + r1];
        }

        // dot over h (K = 64)
        ull acc0 = 0ull, acc1 = 0ull;
        const ulonglong2* xp = reinterpret_cast<const ulonglong2*>(&xh[grp][0]);
        #pragma unroll
        for (int q = 0; q < HID / 4; q++) {
            ulonglong2 a = xp[q];
            fma2(acc0, w0[2 * q],     a.x);
            fma2(acc0, w0[2 * q + 1], a.y);
            fma2(acc1, w1[2 * q],     a.x);
            fma2(acc1, w1[2 * q + 1], a.y);
        }
        gsm[grp][r0] = red2(acc0) + a0;
        gsm[grp][r1] = red2(acc1) + a1;

        if (grp == 0) asm volatile("bar.sync 1, 128;" ::: "memory");
        else          asm volatile("bar.sync 2, 128;" ::: "memory");

        if (upd) {
            float gi = gsm[grp][j];
            float gf = gsm[grp][HID + j];
            float gg = gsm[grp][2 * HID + j];
            float go = gsm[grp][3 * HID + j];
            c = fsigm(gf) * c + fsigm(gi) * ftanh(gg);
            float h = fsigm(go) * ftanh(c);
            xh[grp][j] = h;
            if (!LAST) hout[((size_t)t * BATCH + b) * HID + j] = h;
        }

        if (grp == 0) asm volatile("bar.sync 1, 128;" ::: "memory");
        else          asm volatile("bar.sync 2, 128;" ::: "memory");

        if (LAST) {
            // one warp per group does the 64-wide softmax
            // grp0: warp3 (l in [96,128)), grp1: warp4 (l in [0,32))
            bool smw = (grp == 0) ? (l >= 96) : (l < 32);
            if (smw) {
                int lane = l & 31;
                float h0 = xh[grp][lane];
                float h1 = xh[grp][32 + lane];
                float m = fmaxf(h0, h1);
                #pragma unroll
                for (int off = 16; off > 0; off >>= 1)
                    m = fmaxf(m, __shfl_xor_sync(0xffffffffu, m, off));
                float e0 = __expf(h0 - m);
                float e1 = __expf(h1 - m);
                float s = e0 + e1;
                #pragma unroll
                for (int off = 16; off > 0; off >>= 1)
                    s += __shfl_xor_sync(0xffffffffu, s, off);
                float inv = __fdividef(1.0f, s);
                size_t base = ((size_t)t * BATCH + b) * HID;
                out[base + lane]      = e0 * inv;
                out[base + 32 + lane] = e1 * inv;
            }
        }
        a0 = n0; a1 = n1;
    }
}

extern "C" void kernel_launch(void* const* d_in, const int* in_sizes, int n_in,
                              void* d_out, int out_size)
{
    const int*   x      = (const int*)d_in[0];     // int32 (JAX x64 disabled)
    const float* emb    = (const float*)d_in[1];
    const float* W_ih1  = (const float*)d_in[2];
    const float* W_hh1  = (const float*)d_in[3];
    const float* b_ih1  = (const float*)d_in[4];
    const float* b_hh1  = (const float*)d_in[5];
    const float* W_ih2  = (const float*)d_in[6];
    const float* W_hh2  = (const float*)d_in[7];
    const float* b_ih2  = (const float*)d_in[8];
    const float* b_hh2  = (const float*)d_in[9];
    const float* W_ih3  = (const float*)d_in[10];
    const float* W_hh3  = (const float*)d_in[11];
    const float* b_ih3  = (const float*)d_in[12];
    const float* b_hh3  = (const float*)d_in[13];
    float* out = (float*)d_out;

    float* xg = nullptr;  cudaGetSymbolAddress((void**)&xg, g_xg);
    float* ha = nullptr;  cudaGetSymbolAddress((void**)&ha, g_ha);
    float* hb = nullptr;  cudaGetSymbolAddress((void**)&hb, g_hb);

    // layer 1
    xg_gemm_kernel<EMBD, 1><<<GEMM_GRID, 256>>>(x, emb, W_ih1, b_ih1, b_hh1, xg);
    rec_kernel<0><<<BATCH / 2, 256>>>(xg, W_hh1, ha, out);
    // layer 2
    xg_gemm_kernel<HID, 0><<<GEMM_GRID, 256>>>(x, ha, W_ih2, b_ih2, b_hh2, xg);
    rec_kernel<0><<<BATCH / 2, 256>>>(xg, W_hh2, hb, out);
    // layer 3 (+ fused softmax)
    xg_gemm_kernel<HID, 0><<<GEMM_GRID, 256>>>(x, hb, W_ih3, b_ih3, b_hh3, xg);
    rec_kernel<1><<<BATCH / 2, 256>>>(xg, W_hh3, nullptr, out);
}

// round 6
// speedup vs baseline: 1.1553x; 1.1553x over previous
#include <cuda_runtime.h>
#include <cstdint>
#include <cstddef>

// xg = X @ W_ih^T + b  precomputed per layer (parallel GEMM, layer 1 fuses the
// embedding gather); recurrence kernels do only the K=64 h @ W_hh^T dot per
// step. Rec CTA = two independent 128-thread groups (one batch column each,
// named barriers). Round-4: depth-4 xg prefetch ring (DRAM latency 577cyc was
// exposed at depth 1), paired gate rows (2l,2l+1) -> single float2 xg load,
// 2 CTAs/SM for the KIN=64 GEMMs.

#define T_SEQ   512
#define BATCH   256
#define HID     64
#define GATES   256   // 4*HID
#define EMBD    128
#define VOCAB   50257
#define GROWS   (T_SEQ * BATCH)
#define RPC     128                // rows per GEMM CTA
#define CHUNK   8                  // rows per smem chunk
#define GEMM_GRID (GROWS / RPC)    // 1024

__device__ float g_xg[(size_t)T_SEQ * BATCH * GATES];
__device__ float g_ha[(size_t)T_SEQ * BATCH * HID];
__device__ float g_hb[(size_t)T_SEQ * BATCH * HID];

typedef unsigned long long ull;

__device__ __forceinline__ ull pack2(float x, float y) {
    ull r; asm("mov.b64 %0, {%1,%2};" : "=l"(r) : "f"(x), "f"(y)); return r;
}
__device__ __forceinline__ void fma2(ull& acc, ull a, ull b) {
    asm("fma.rn.f32x2 %0, %1, %2, %0;" : "+l"(acc) : "l"(a), "l"(b));
}
__device__ __forceinline__ float red2(ull a) {
    float lo, hi; asm("mov.b64 {%0,%1}, %2;" : "=f"(lo), "=f"(hi) : "l"(a));
    return lo + hi;
}
__device__ __forceinline__ float fsigm(float x) {
    return __fdividef(1.0f, 1.0f + __expf(-x));
}
__device__ __forceinline__ float ftanh(float x) {
    return 2.0f * fsigm(2.0f * x) - 1.0f;
}

// ---------------------------------------------------------------------------
// xg GEMM: xg[r][g] = sum_k X[r][k] * W_ih[g][k] + b_ih[g] + b_hh[g]
// ---------------------------------------------------------------------------
template <int KIN, int GATHER>
__global__ void __launch_bounds__(256, 128 / KIN)    // KIN=64 -> 2 CTAs/SM
xg_gemm_kernel(const int* __restrict__ xidx,
               const float* __restrict__ src,
               const float* __restrict__ W_ih,
               const float* __restrict__ b_ih,
               const float* __restrict__ b_hh,
               float* __restrict__ xg)
{
    __shared__ __align__(16) float xs[CHUNK][KIN];
    const int tid = threadIdx.x;
    const int g = tid;
    const int rbase0 = blockIdx.x * RPC;

    ull w2[KIN / 2];
    {
        const float4* wi = reinterpret_cast<const float4*>(W_ih + (size_t)g * KIN);
        #pragma unroll
        for (int q = 0; q < KIN / 4; q++) {
            float4 v = wi[q];
            w2[2 * q]     = pack2(v.x, v.y);
            w2[2 * q + 1] = pack2(v.z, v.w);
        }
    }
    const float bs = b_ih[g] + b_hh[g];

    constexpr int PF = CHUNK * KIN / 256;    // 4 (KIN=128) or 2 (KIN=64)
    const int prow = (tid * PF) / KIN;
    const int pk   = (tid * PF) % KIN;

    float pf[PF];
    auto prefetch = [&](int cb) {
        int r = rbase0 + cb + prow;
        const float* sp;
        if (GATHER) {
            int tok = xidx[r];
            tok = tok < 0 ? 0 : (tok >= VOCAB ? VOCAB - 1 : tok);
            sp = src + (size_t)tok * EMBD + pk;
        } else {
            sp = src + (size_t)r * KIN + pk;
        }
        if (PF == 4) {
            float4 v = *reinterpret_cast<const float4*>(sp);
            pf[0] = v.x; pf[1] = v.y; pf[2] = v.z; pf[3] = v.w;
        } else {
            float2 v = *reinterpret_cast<const float2*>(sp);
            pf[0] = v.x; pf[1] = v.y;
        }
    };

    prefetch(0);

    for (int cb = 0; cb < RPC; cb += CHUNK) {
        __syncthreads();
        #pragma unroll
        for (int i = 0; i < PF; i++) xs[prow][pk + i] = pf[i];
        __syncthreads();
        if (cb + CHUNK < RPC) prefetch(cb + CHUNK);

        ull acc[CHUNK];
        #pragma unroll
        for (int row = 0; row < CHUNK; row++) acc[row] = 0ull;
        #pragma unroll
        for (int q = 0; q < KIN / 4; q++) {
            #pragma unroll
            for (int row = 0; row < CHUNK; row++) {
                ulonglong2 a = reinterpret_cast<const ulonglong2*>(&xs[row][0])[q];
                fma2(acc[row], w2[2 * q],     a.x);
                fma2(acc[row], w2[2 * q + 1], a.y);
            }
        }
        #pragma unroll
        for (int row = 0; row < CHUNK; row++) {
            xg[(size_t)(rbase0 + cb + row) * GATES + g] = red2(acc[row]) + bs;
        }
    }
}

// ---------------------------------------------------------------------------
// Recurrence. Thread l of a 128-thread group owns gate rows 2l, 2l+1 of its
// batch column -> xg arrives as one float2, gsm written as one float2.
// Depth-4 register ring hides the 577-cycle DRAM latency of the xg stream.
// ---------------------------------------------------------------------------
template <int LAST>
__global__ void __launch_bounds__(256, 1)
rec_kernel(const float* __restrict__ xg,
           const float* __restrict__ W_hh,
           float* __restrict__ hout,
           float* __restrict__ out)
{
    __shared__ __align__(16) float xh[2][HID];
    __shared__ __align__(8)  float gsm[2][GATES];

    const int tid = threadIdx.x;
    const int grp = tid >> 7;
    const int l   = tid & 127;
    const int b   = blockIdx.x * 2 + grp;
    const int r0  = 2 * l;                 // rows r0, r0+1

    ull w0[HID / 2], w1[HID / 2];
    {
        const float4* wa = reinterpret_cast<const float4*>(W_hh + (size_t)r0 * HID);
        const float4* wb = reinterpret_cast<const float4*>(W_hh + (size_t)(r0 + 1) * HID);
        #pragma unroll
        for (int q = 0; q < HID / 4; q++) {
            float4 va = wa[q];
            w0[2 * q]     = pack2(va.x, va.y);
            w0[2 * q + 1] = pack2(va.z, va.w);
            float4 vb = wb[q];
            w1[2 * q]     = pack2(vb.x, vb.y);
            w1[2 * q + 1] = pack2(vb.z, vb.w);
        }
    }

    // update threads: grp0 -> warps 0,1 (SMSP 0,1); grp1 -> warps 6,7 (SMSP 2,3)
    const bool upd = (grp == 0) ? (l < HID) : (l >= 128 - HID);
    const int  j   = (grp == 0) ? l : (l - (128 - HID));

    if (l < HID) xh[grp][l] = 0.0f;
    float c = 0.0f;
    __syncthreads();

    // depth-4 prefetch ring
    float2 xbuf[4];
    #pragma unroll
    for (int p = 0; p < 4; p++)
        xbuf[p] = *reinterpret_cast<const float2*>(
            xg + ((size_t)p * BATCH + b) * GATES + r0);

    #pragma unroll 4
    for (int t = 0; t < T_SEQ; t++) {
        const int p = t & 3;
        float2 cur = xbuf[p];
        if (t + 4 < T_SEQ)
            xbuf[p] = *reinterpret_cast<const float2*>(
                xg + ((size_t)(t + 4) * BATCH + b) * GATES + r0);

        // dot over h (K = 64) for rows r0, r0+1
        ull acc0 = 0ull, acc1 = 0ull;
        const ulonglong2* xp = reinterpret_cast<const ulonglong2*>(&xh[grp][0]);
        #pragma unroll
        for (int q = 0; q < HID / 4; q++) {
            ulonglong2 a = xp[q];
            fma2(acc0, w0[2 * q],     a.x);
            fma2(acc0, w0[2 * q + 1], a.y);
            fma2(acc1, w1[2 * q],     a.x);
            fma2(acc1, w1[2 * q + 1], a.y);
        }
        *reinterpret_cast<float2*>(&gsm[grp][r0]) =
            make_float2(red2(acc0) + cur.x, red2(acc1) + cur.y);

        if (grp == 0) asm volatile("bar.sync 1, 128;" ::: "memory");
        else          asm volatile("bar.sync 2, 128;" ::: "memory");

        if (upd) {
            float gi = gsm[grp][j];
            float gf = gsm[grp][HID + j];
            float gg = gsm[grp][2 * HID + j];
            float go = gsm[grp][3 * HID + j];
            c = fsigm(gf) * c + fsigm(gi) * ftanh(gg);
            float h = fsigm(go) * ftanh(c);
            xh[grp][j] = h;
            if (!LAST) hout[((size_t)t * BATCH + b) * HID + j] = h;
        }

        if (grp == 0) asm volatile("bar.sync 1, 128;" ::: "memory");
        else          asm volatile("bar.sync 2, 128;" ::: "memory");

        if (LAST) {
            bool smw = (grp == 0) ? (l >= 96) : (l < 32);
            if (smw) {
                int lane = l & 31;
                float h0 = xh[grp][lane];
                float h1 = xh[grp][32 + lane];
                float m = fmaxf(h0, h1);
                #pragma unroll
                for (int off = 16; off > 0; off >>= 1)
                    m = fmaxf(m, __shfl_xor_sync(0xffffffffu, m, off));
                float e0 = __expf(h0 - m);
                float e1 = __expf(h1 - m);
                float s = e0 + e1;
                #pragma unroll
                for (int off = 16; off > 0; off >>= 1)
                    s += __shfl_xor_sync(0xffffffffu, s, off);
                float inv = __fdividef(1.0f, s);
                size_t base = ((size_t)t * BATCH + b) * HID;
                out[base + lane]      = e0 * inv;
                out[base + 32 + lane] = e1 * inv;
            }
        }
    }
}

extern "C" void kernel_launch(void* const* d_in, const int* in_sizes, int n_in,
                              void* d_out, int out_size)
{
    const int*   x      = (const int*)d_in[0];     // int32 (JAX x64 disabled)
    const float* emb    = (const float*)d_in[1];
    const float* W_ih1  = (const float*)d_in[2];
    const float* W_hh1  = (const float*)d_in[3];
    const float* b_ih1  = (const float*)d_in[4];
    const float* b_hh1  = (const float*)d_in[5];
    const float* W_ih2  = (const float*)d_in[6];
    const float* W_hh2  = (const float*)d_in[7];
    const float* b_ih2  = (const float*)d_in[8];
    const float* b_hh2  = (const float*)d_in[9];
    const float* W_ih3  = (const float*)d_in[10];
    const float* W_hh3  = (const float*)d_in[11];
    const float* b_ih3  = (const float*)d_in[12];
    const float* b_hh3  = (const float*)d_in[13];
    float* out = (float*)d_out;

    float* xg = nullptr;  cudaGetSymbolAddress((void**)&xg, g_xg);
    float* ha = nullptr;  cudaGetSymbolAddress((void**)&ha, g_ha);
    float* hb = nullptr;  cudaGetSymbolAddress((void**)&hb, g_hb);

    xg_gemm_kernel<EMBD, 1><<<GEMM_GRID, 256>>>(x, emb, W_ih1, b_ih1, b_hh1, xg);
    rec_kernel<0><<<BATCH / 2, 256>>>(xg, W_hh1, ha, out);
    xg_gemm_kernel<HID, 0><<<GEMM_GRID, 256>>>(x, ha, W_ih2, b_ih2, b_hh2, xg);
    rec_kernel<0><<<BATCH / 2, 256>>>(xg, W_hh2, hb, out);
    xg_gemm_kernel<HID, 0><<<GEMM_GRID, 256>>>(x, hb, W_ih3, b_ih3, b_hh3, xg);
    rec_kernel<1><<<BATCH / 2, 256>>>(xg, W_hh3, nullptr, out);
}